// round 12
// baseline (speedup 1.0000x reference)
#include <cuda_runtime.h>
#include <cuda_bf16.h>
#include <cstdint>

// ---------------------------------------------------------------------------
// MLA forward. tf32 mma.sync GEMMs (cp.async pipelines) + fused flash
// attention (scores + softmax + attn@V in one kernel, no scores buffer).
// P fragments staged per-warp through SMEM (no cross-lane shuffles).
//   B=2, S=2048, D=2048, H=16, DH=128, DL=512
// ---------------------------------------------------------------------------

#define BDIM 2
#define SEQ 2048
#define DMODEL 2048
#define NHEAD 16
#define DHEAD 128
#define DLAT 512
#define ROWS (BDIM * SEQ)          // 4096

__device__ float g_z[(size_t)ROWS * DLAT];
__device__ float g_q[(size_t)ROWS * DMODEL];
__device__ float g_k[(size_t)NHEAD * ROWS * DHEAD];
__device__ float g_v[(size_t)NHEAD * ROWS * DHEAD];
__device__ float g_ao[(size_t)ROWS * DMODEL];

// tf32-rounded copies of harness inputs
__device__ float g_xc[(size_t)ROWS * DMODEL];
__device__ float g_wlat[(size_t)DMODEL * DLAT];
__device__ float g_wq[(size_t)DMODEL * DMODEL];
__device__ float g_wk[(size_t)NHEAD * DLAT * DHEAD];
__device__ float g_wv[(size_t)NHEAD * DLAT * DHEAD];
__device__ float g_wo[(size_t)DMODEL * DMODEL];

#define BM 128
#define BN 128
#define BKT 16

// ---------------- helpers ----------------

__device__ __forceinline__ float cvt_tf32(float v)
{
    uint32_t u;
    asm("cvt.rna.tf32.f32 %0, %1;" : "=r"(u) : "f"(v));
    return __uint_as_float(u);
}

__device__ __forceinline__ float4 cvt_tf32_4(float4 v)
{
    float4 r;
    r.x = cvt_tf32(v.x); r.y = cvt_tf32(v.y);
    r.z = cvt_tf32(v.z); r.w = cvt_tf32(v.w);
    return r;
}

__device__ __forceinline__ void cp_async16(void* smem_dst, const void* gmem_src)
{
    uint32_t s = (uint32_t)__cvta_generic_to_shared(smem_dst);
    asm volatile("cp.async.cg.shared.global [%0], [%1], 16;\n" :: "r"(s), "l"(gmem_src));
}
__device__ __forceinline__ void cp_commit()
{
    asm volatile("cp.async.commit_group;\n");
}
template <int N>
__device__ __forceinline__ void cp_wait()
{
    asm volatile("cp.async.wait_group %0;\n" :: "n"(N));
}

#define MMA_TF32(acc, a0, a1, a2, a3, b0, b1)                                  \
    asm volatile(                                                              \
        "mma.sync.aligned.m16n8k8.row.col.f32.tf32.tf32.f32 "                  \
        "{%0,%1,%2,%3},{%4,%5,%6,%7},{%8,%9},{%0,%1,%2,%3};\n"                 \
        : "+f"((acc)[0]), "+f"((acc)[1]), "+f"((acc)[2]), "+f"((acc)[3])       \
        : "r"(a0), "r"(a1), "r"(a2), "r"(a3), "r"(b0), "r"(b1))

// ---------------- GEMM core (projections) ----------------
template <bool TRANSB, bool RND>
__device__ __forceinline__ void gemm_tc(
    const float* __restrict__ A, int lda,
    const float* __restrict__ B, int ldb,
    const float* __restrict__ bias,
    float* __restrict__ C, int ldc,
    int K, float alpha)
{
    constexpr int ASTR = BKT + 4;
    constexpr int BSTR_NN = BN + 8;
    constexpr int BS_SZ = TRANSB ? (BN * ASTR) : (BKT * BSTR_NN);

    __shared__ float As[2][BM * ASTR];
    __shared__ float Bs[2][BS_SZ];

    const int tid = threadIdx.x;
    const int lane = tid & 31;
    const int wid = tid >> 5;
    const int wm = wid & 1;
    const int wn = wid >> 1;
    const int grp = lane >> 2;
    const int qid = lane & 3;

    const int m0 = blockIdx.y * BM;
    const int n0 = blockIdx.x * BN;

    auto issue = [&](int buf, int k0) {
        #pragma unroll
        for (int p = 0; p < 2; p++) {
            const int id = tid + 256 * p;
            cp_async16(&As[buf][(id >> 2) * ASTR + (id & 3) * 4],
                       &A[(size_t)(m0 + (id >> 2)) * lda + k0 + (id & 3) * 4]);
            if (TRANSB) {
                cp_async16(&Bs[buf][(id >> 2) * ASTR + (id & 3) * 4],
                           &B[(size_t)(n0 + (id >> 2)) * ldb + k0 + (id & 3) * 4]);
            } else {
                cp_async16(&Bs[buf][(id >> 5) * BSTR_NN + (id & 31) * 4],
                           &B[(size_t)(k0 + (id >> 5)) * ldb + n0 + (id & 31) * 4]);
            }
        }
        cp_commit();
    };

    float acc[4][4][4];
    #pragma unroll
    for (int mi = 0; mi < 4; mi++)
        #pragma unroll
        for (int ni = 0; ni < 4; ni++)
            #pragma unroll
            for (int r = 0; r < 4; r++) acc[mi][ni][r] = 0.0f;

    auto compute = [&](int buf) {
        #pragma unroll
        for (int ks = 0; ks < BKT / 8; ks++) {
            uint32_t af[4][4];
            uint32_t bf[4][2];
            const int kc = ks * 8 + qid;
            #pragma unroll
            for (int mi = 0; mi < 4; mi++) {
                const int r = wm * 64 + mi * 16 + grp;
                af[mi][0] = __float_as_uint(As[buf][(r) * ASTR + kc]);
                af[mi][1] = __float_as_uint(As[buf][(r + 8) * ASTR + kc]);
                af[mi][2] = __float_as_uint(As[buf][(r) * ASTR + kc + 4]);
                af[mi][3] = __float_as_uint(As[buf][(r + 8) * ASTR + kc + 4]);
            }
            #pragma unroll
            for (int ni = 0; ni < 4; ni++) {
                const int n = wn * 32 + ni * 8 + grp;
                if (TRANSB) {
                    bf[ni][0] = __float_as_uint(Bs[buf][n * ASTR + kc]);
                    bf[ni][1] = __float_as_uint(Bs[buf][n * ASTR + kc + 4]);
                } else {
                    bf[ni][0] = __float_as_uint(Bs[buf][(kc) * BSTR_NN + n]);
                    bf[ni][1] = __float_as_uint(Bs[buf][(kc + 4) * BSTR_NN + n]);
                }
            }
            #pragma unroll
            for (int mi = 0; mi < 4; mi++)
                #pragma unroll
                for (int ni = 0; ni < 4; ni++)
                    MMA_TF32(acc[mi][ni], af[mi][0], af[mi][1], af[mi][2],
                             af[mi][3], bf[ni][0], bf[ni][1]);
        }
    };

    const int nchunk = K / BKT;
    issue(0, 0);
    for (int c = 0; c < nchunk; c++) {
        if (c + 1 < nchunk) {
            issue((c + 1) & 1, (c + 1) * BKT);
            cp_wait<1>();
        } else {
            cp_wait<0>();
        }
        __syncthreads();
        compute(c & 1);
        __syncthreads();
    }

    const int row0 = m0 + wm * 64 + grp;
    const int col00 = n0 + wn * 32 + qid * 2;
    #pragma unroll
    for (int mi = 0; mi < 4; mi++) {
        #pragma unroll
        for (int ni = 0; ni < 4; ni++) {
            const int col = col00 + ni * 8;
            float bx = 0.0f, by = 0.0f;
            if (bias) { bx = bias[col]; by = bias[col + 1]; }
            const int r0 = row0 + mi * 16;
            float2 v0, v1;
            v0.x = acc[mi][ni][0] * alpha + bx;
            v0.y = acc[mi][ni][1] * alpha + by;
            v1.x = acc[mi][ni][2] * alpha + bx;
            v1.y = acc[mi][ni][3] * alpha + by;
            if (RND) {
                v0.x = cvt_tf32(v0.x); v0.y = cvt_tf32(v0.y);
                v1.x = cvt_tf32(v1.x); v1.y = cvt_tf32(v1.y);
            }
            *reinterpret_cast<float2*>(&C[(size_t)r0 * ldc + col]) = v0;
            *reinterpret_cast<float2*>(&C[(size_t)(r0 + 8) * ldc + col]) = v1;
        }
    }
}

// ---------------- input rounding pre-pass ----------------
__global__ __launch_bounds__(256)
void k_cvt(const float* __restrict__ in, float* __restrict__ out, int n4)
{
    const int i = blockIdx.x * 256 + threadIdx.x;
    if (i < n4) {
        reinterpret_cast<float4*>(out)[i] =
            cvt_tf32_4(reinterpret_cast<const float4*>(in)[i]);
    }
}

// ---------------- GEMM wrappers ----------------

__global__ __launch_bounds__(256, 2)
void k_proj_z(const float* __restrict__ b)
{
    gemm_tc<false, true>(g_xc, DMODEL, g_wlat, DLAT, b, g_z, DLAT, DMODEL, 1.0f);
}

__global__ __launch_bounds__(256, 2)
void k_proj_q(const float* __restrict__ b)
{
    gemm_tc<false, true>(g_xc, DMODEL, g_wq, DMODEL, b, g_q, DMODEL, DMODEL, 1.0f);
}

__global__ __launch_bounds__(256, 2)
void k_proj_kv(const float* __restrict__ bk, const float* __restrict__ bv)
{
    const int zb = blockIdx.z;
    const int h = zb & (NHEAD - 1);
    const bool isv = zb >= NHEAD;
    const float* w = (isv ? g_wv : g_wk) + (size_t)h * DLAT * DHEAD;
    const float* bb = (isv ? bv : bk) + (size_t)h * DHEAD;
    float* C = (isv ? g_v : g_k) + (size_t)h * ROWS * DHEAD;
    gemm_tc<false, true>(g_z, DLAT, w, DHEAD, bb, C, DHEAD, DLAT, 1.0f);
}

__global__ __launch_bounds__(256, 2)
void k_proj_out(const float* __restrict__ b, float* __restrict__ out)
{
    gemm_tc<false, false>(g_ao, DMODEL, g_wo, DMODEL, b, out, DMODEL, DMODEL, 1.0f);
}

// ---------------- fused flash attention ----------------
// grid (16 q-tiles, 32 bh). 256 thr, 8 warps; warp w owns rows w*16..w*16+15.
// Q tile 128x128 resident; K/V streamed in 32-key tiles, double-buffered.
// P staged per-warp in SMEM: write with C-fragment layout, read with
// A-fragment layout (both proven in gemm_tc). No cross-warp P traffic.
// NOTE: a row of 128 floats = 512 B = 32 x 16B chunks (R9/R10 loaded only 8!).
#define TQ 128
#define TK 32
#define QSTR 132
#define KSTR 132
#define VSTR 136
#define PSTR 36
#define NIT (SEQ / TK)                     // 64
#define QOFF 0
#define KOFF (TQ * QSTR)                   // 16896
#define VOFF (KOFF + 2 * TK * KSTR)        // 25344
#define POFF (VOFF + 2 * TK * VSTR)        // 34048
#define FL_SMEM ((POFF + TQ * PSTR) * 4)   // 154624 B

__global__ __launch_bounds__(256, 1)
void k_flash()
{
    extern __shared__ float sm[];
    float* Qs = sm + QOFF;
    float* Ps = sm + POFF;

    const int tid = threadIdx.x;
    const int lane = tid & 31;
    const int wid = tid >> 5;
    const int grp = lane >> 2;
    const int qid = lane & 3;

    const int bh = blockIdx.y;
    const int b = bh >> 4;
    const int h = bh & (NHEAD - 1);
    const int q0 = blockIdx.x * TQ;

    const float* Qg = g_q + ((size_t)b * SEQ + q0) * DMODEL + h * DHEAD;
    const float* Kg = g_k + ((size_t)h * ROWS + (size_t)b * SEQ) * DHEAD;
    const float* Vg = g_v + ((size_t)h * ROWS + (size_t)b * SEQ) * DHEAD;
    float* Og = g_ao + ((size_t)b * SEQ + q0) * DMODEL + h * DHEAD;

    // K/V tile: 32 rows x 32 chunks of 16B = 1024 chunks each -> 4/thread
    auto issue_kv = [&](int buf, int it) {
        float* Ks = sm + KOFF + buf * (TK * KSTR);
        float* Vs = sm + VOFF + buf * (TK * VSTR);
        #pragma unroll
        for (int p = 0; p < 4; p++) {
            const int id = tid + 256 * p;
            const int row = id >> 5;          // 0..31
            const int ch = id & 31;           // 0..31 (x4 floats)
            cp_async16(&Ks[row * KSTR + ch * 4],
                       &Kg[((size_t)it * TK + row) * DHEAD + ch * 4]);
            cp_async16(&Vs[row * VSTR + ch * 4],
                       &Vg[((size_t)it * TK + row) * DHEAD + ch * 4]);
        }
    };

    // prologue: Q (128 rows x 32 chunks = 4096 chunks -> 16/thread) + K0/V0
    #pragma unroll
    for (int p = 0; p < 16; p++) {
        const int id = tid + 256 * p;
        const int row = id >> 5;              // 0..127
        const int ch = id & 31;               // 0..31
        cp_async16(&Qs[row * QSTR + ch * 4],
                   &Qg[(size_t)row * DMODEL + ch * 4]);
    }
    issue_kv(0, 0);
    cp_commit();

    // online softmax state (rows grp, grp+8 of this warp's 16)
    float m0 = -3.4e38f, m1 = -3.4e38f, l0 = 0.0f, l1 = 0.0f;
    float acco[16][4];
    #pragma unroll
    for (int ni = 0; ni < 16; ni++)
        #pragma unroll
        for (int r = 0; r < 4; r++) acco[ni][r] = 0.0f;

    const int qrow = wid * 16 + grp;     // this thread's row (and +8)
    const float sc = 0.08838834764831845f;   // 1/sqrt(128)

    for (int it = 0; it < NIT; it++) {
        const int buf = it & 1;
        if (it + 1 < NIT) {
            issue_kv(buf ^ 1, it + 1);
            cp_commit();
            cp_wait<1>();
        } else {
            cp_wait<0>();
        }
        __syncthreads();

        const float* Ks = sm + KOFF + buf * (TK * KSTR);
        const float* Vs = sm + VOFF + buf * (TK * VSTR);

        // ---- S = Q . K^T  (warp tile 16 x 32, K-dim 128) ----
        float accs[4][4];
        #pragma unroll
        for (int ni = 0; ni < 4; ni++)
            #pragma unroll
            for (int r = 0; r < 4; r++) accs[ni][r] = 0.0f;

        #pragma unroll
        for (int ks = 0; ks < 16; ks++) {
            const int kc = ks * 8 + qid;
            const uint32_t a0 = __float_as_uint(Qs[qrow * QSTR + kc]);
            const uint32_t a1 = __float_as_uint(Qs[(qrow + 8) * QSTR + kc]);
            const uint32_t a2 = __float_as_uint(Qs[qrow * QSTR + kc + 4]);
            const uint32_t a3 = __float_as_uint(Qs[(qrow + 8) * QSTR + kc + 4]);
            #pragma unroll
            for (int ni = 0; ni < 4; ni++) {
                const int n = ni * 8 + grp;
                const uint32_t b0 = __float_as_uint(Ks[n * KSTR + kc]);
                const uint32_t b1 = __float_as_uint(Ks[n * KSTR + kc + 4]);
                MMA_TF32(accs[ni], a0, a1, a2, a3, b0, b1);
            }
        }

        // ---- online softmax (rows grp / grp+8; cols ni*8 + qid*2 +{0,1}) ----
        float rm0 = -3.4e38f, rm1 = -3.4e38f;
        #pragma unroll
        for (int ni = 0; ni < 4; ni++) {
            accs[ni][0] *= sc; accs[ni][1] *= sc;
            accs[ni][2] *= sc; accs[ni][3] *= sc;
            rm0 = fmaxf(rm0, fmaxf(accs[ni][0], accs[ni][1]));
            rm1 = fmaxf(rm1, fmaxf(accs[ni][2], accs[ni][3]));
        }
        rm0 = fmaxf(rm0, __shfl_xor_sync(0xffffffffu, rm0, 1));
        rm0 = fmaxf(rm0, __shfl_xor_sync(0xffffffffu, rm0, 2));
        rm1 = fmaxf(rm1, __shfl_xor_sync(0xffffffffu, rm1, 1));
        rm1 = fmaxf(rm1, __shfl_xor_sync(0xffffffffu, rm1, 2));

        const float nm0 = fmaxf(m0, rm0);
        const float nm1 = fmaxf(m1, rm1);
        const float f0 = __expf(m0 - nm0);
        const float f1 = __expf(m1 - nm1);
        m0 = nm0; m1 = nm1;

        float rs0 = 0.0f, rs1 = 0.0f;
        #pragma unroll
        for (int ni = 0; ni < 4; ni++) {
            accs[ni][0] = __expf(accs[ni][0] - nm0);
            accs[ni][1] = __expf(accs[ni][1] - nm0);
            accs[ni][2] = __expf(accs[ni][2] - nm1);
            accs[ni][3] = __expf(accs[ni][3] - nm1);
            rs0 += accs[ni][0] + accs[ni][1];
            rs1 += accs[ni][2] + accs[ni][3];
        }
        rs0 += __shfl_xor_sync(0xffffffffu, rs0, 1);
        rs0 += __shfl_xor_sync(0xffffffffu, rs0, 2);
        rs1 += __shfl_xor_sync(0xffffffffu, rs1, 1);
        rs1 += __shfl_xor_sync(0xffffffffu, rs1, 2);
        l0 = l0 * f0 + rs0;
        l1 = l1 * f1 + rs1;

        // ---- stage P through SMEM (C-frag write, per-warp region) ----
        #pragma unroll
        for (int ni = 0; ni < 4; ni++) {
            float2 p0, p1;
            p0.x = cvt_tf32(accs[ni][0]); p0.y = cvt_tf32(accs[ni][1]);
            p1.x = cvt_tf32(accs[ni][2]); p1.y = cvt_tf32(accs[ni][3]);
            *reinterpret_cast<float2*>(
                &Ps[(size_t)qrow * PSTR + ni * 8 + qid * 2]) = p0;
            *reinterpret_cast<float2*>(
                &Ps[(size_t)(qrow + 8) * PSTR + ni * 8 + qid * 2]) = p1;
        }
        __syncwarp();

        // rescale O
        #pragma unroll
        for (int ni = 0; ni < 16; ni++) {
            acco[ni][0] *= f0; acco[ni][1] *= f0;
            acco[ni][2] *= f1; acco[ni][3] *= f1;
        }

        // ---- O += P . V  (A-frag read of P, proven pattern) ----
        #pragma unroll
        for (int ks = 0; ks < 4; ks++) {
            const int kc = ks * 8 + qid;
            const uint32_t a0 = __float_as_uint(Ps[qrow * PSTR + kc]);
            const uint32_t a1 = __float_as_uint(Ps[(qrow + 8) * PSTR + kc]);
            const uint32_t a2 = __float_as_uint(Ps[qrow * PSTR + kc + 4]);
            const uint32_t a3 = __float_as_uint(Ps[(qrow + 8) * PSTR + kc + 4]);
            #pragma unroll
            for (int ni = 0; ni < 16; ni++) {
                const int n = ni * 8 + grp;
                const uint32_t b0 = __float_as_uint(Vs[kc * VSTR + n]);
                const uint32_t b1 = __float_as_uint(Vs[(kc + 4) * VSTR + n]);
                MMA_TF32(acco[ni], a0, a1, a2, a3, b0, b1);
            }
        }
        __syncthreads();   // K/V buffers + P reusable next iteration
    }

    // ---- epilogue: O /= l, round to tf32, store ----
    const float inv0 = 1.0f / l0;
    const float inv1 = 1.0f / l1;
    #pragma unroll
    for (int ni = 0; ni < 16; ni++) {
        const int col = ni * 8 + qid * 2;
        float2 v0, v1;
        v0.x = cvt_tf32(acco[ni][0] * inv0);
        v0.y = cvt_tf32(acco[ni][1] * inv0);
        v1.x = cvt_tf32(acco[ni][2] * inv1);
        v1.y = cvt_tf32(acco[ni][3] * inv1);
        *reinterpret_cast<float2*>(&Og[(size_t)qrow * DMODEL + col]) = v0;
        *reinterpret_cast<float2*>(&Og[(size_t)(qrow + 8) * DMODEL + col]) = v1;
    }
}

// ---------------- launch ----------------

extern "C" void kernel_launch(void* const* d_in, const int* in_sizes, int n_in,
                              void* d_out, int out_size)
{
    const float* x        = (const float*)d_in[0];
    const float* w_latent = (const float*)d_in[1];
    const float* b_latent = (const float*)d_in[2];
    const float* w_q      = (const float*)d_in[3];
    const float* b_q      = (const float*)d_in[4];
    const float* w_k      = (const float*)d_in[5];
    const float* b_k      = (const float*)d_in[6];
    const float* w_v      = (const float*)d_in[7];
    const float* b_v      = (const float*)d_in[8];
    const float* w_o      = (const float*)d_in[9];
    const float* b_o      = (const float*)d_in[10];
    float* out            = (float*)d_out;

    dim3 blk(256);

    cudaFuncSetAttribute(k_flash,
                         cudaFuncAttributeMaxDynamicSharedMemorySize, FL_SMEM);

    float *p_xc, *p_wlat, *p_wq, *p_wk, *p_wv, *p_wo;
    cudaGetSymbolAddress((void**)&p_xc,   g_xc);
    cudaGetSymbolAddress((void**)&p_wlat, g_wlat);
    cudaGetSymbolAddress((void**)&p_wq,   g_wq);
    cudaGetSymbolAddress((void**)&p_wk,   g_wk);
    cudaGetSymbolAddress((void**)&p_wv,   g_wv);
    cudaGetSymbolAddress((void**)&p_wo,   g_wo);

    auto cvt = [&](const float* src, float* dst, size_t n) {
        const int n4 = (int)(n / 4);
        k_cvt<<<(n4 + 255) / 256, blk>>>(src, dst, n4);
    };
    cvt(x,        p_xc,   (size_t)ROWS * DMODEL);
    cvt(w_latent, p_wlat, (size_t)DMODEL * DLAT);
    cvt(w_q,      p_wq,   (size_t)DMODEL * DMODEL);
    cvt(w_k,      p_wk,   (size_t)NHEAD * DLAT * DHEAD);
    cvt(w_v,      p_wv,   (size_t)NHEAD * DLAT * DHEAD);
    cvt(w_o,      p_wo,   (size_t)DMODEL * DMODEL);

    k_proj_z<<<dim3(DLAT / BN, ROWS / BM), blk>>>(b_latent);
    k_proj_q<<<dim3(DMODEL / BN, ROWS / BM), blk>>>(b_q);
    k_proj_kv<<<dim3(DHEAD / BN, ROWS / BM, 2 * NHEAD), blk>>>(b_k, b_v);
    k_flash<<<dim3(SEQ / TQ, BDIM * NHEAD), blk, FL_SMEM>>>();
    k_proj_out<<<dim3(DMODEL / BN, ROWS / BM), blk>>>(b_o, out);
}

// round 13
// speedup vs baseline: 1.4351x; 1.4351x over previous
#include <cuda_runtime.h>
#include <cuda_bf16.h>
#include <cstdint>

// ---------------------------------------------------------------------------
// MLA forward. tf32 mma.sync GEMMs with 3-stage cp.async pipeline
// (one __syncthreads per K-chunk). Unfused attention (scores/softmax/attn_v)
// — fused flash measured slower (R12: 1985 vs 1427 us).
//   B=2, S=2048, D=2048, H=16, DH=128, DL=512
// ---------------------------------------------------------------------------

#define BDIM 2
#define SEQ 2048
#define DMODEL 2048
#define NHEAD 16
#define DHEAD 128
#define DLAT 512
#define ROWS (BDIM * SEQ)          // 4096

__device__ float g_z[(size_t)ROWS * DLAT];
__device__ float g_q[(size_t)ROWS * DMODEL];
__device__ float g_k[(size_t)NHEAD * ROWS * DHEAD];
__device__ float g_v[(size_t)NHEAD * ROWS * DHEAD];
__device__ float g_scores[(size_t)BDIM * NHEAD * SEQ * SEQ];   // 512 MB
__device__ float g_ao[(size_t)ROWS * DMODEL];

// tf32-rounded copies of harness inputs
__device__ float g_xc[(size_t)ROWS * DMODEL];
__device__ float g_wlat[(size_t)DMODEL * DLAT];
__device__ float g_wq[(size_t)DMODEL * DMODEL];
__device__ float g_wk[(size_t)NHEAD * DLAT * DHEAD];
__device__ float g_wv[(size_t)NHEAD * DLAT * DHEAD];
__device__ float g_wo[(size_t)DMODEL * DMODEL];

#define BM 128
#define BN 128
#define BKT 16
#define STAGES 3
#define ASTR 20                      // BKT + 4
#define BSTR_NN 136                  // BN + 8

// smem bytes per instantiation
#define SMEM_T  (STAGES * (BM * ASTR + BN * ASTR) * 4)        // 61440
#define SMEM_N  (STAGES * (BM * ASTR + BKT * BSTR_NN) * 4)    // 56832

// ---------------- helpers ----------------

__device__ __forceinline__ float cvt_tf32(float v)
{
    uint32_t u;
    asm("cvt.rna.tf32.f32 %0, %1;" : "=r"(u) : "f"(v));
    return __uint_as_float(u);
}

__device__ __forceinline__ float4 cvt_tf32_4(float4 v)
{
    float4 r;
    r.x = cvt_tf32(v.x); r.y = cvt_tf32(v.y);
    r.z = cvt_tf32(v.z); r.w = cvt_tf32(v.w);
    return r;
}

__device__ __forceinline__ void cp_async16(void* smem_dst, const void* gmem_src)
{
    uint32_t s = (uint32_t)__cvta_generic_to_shared(smem_dst);
    asm volatile("cp.async.cg.shared.global [%0], [%1], 16;\n" :: "r"(s), "l"(gmem_src));
}
__device__ __forceinline__ void cp_commit()
{
    asm volatile("cp.async.commit_group;\n");
}
template <int N>
__device__ __forceinline__ void cp_wait()
{
    asm volatile("cp.async.wait_group %0;\n" :: "n"(N));
}

#define MMA_TF32(acc, a0, a1, a2, a3, b0, b1)                                  \
    asm volatile(                                                              \
        "mma.sync.aligned.m16n8k8.row.col.f32.tf32.tf32.f32 "                  \
        "{%0,%1,%2,%3},{%4,%5,%6,%7},{%8,%9},{%0,%1,%2,%3};\n"                 \
        : "+f"((acc)[0]), "+f"((acc)[1]), "+f"((acc)[2]), "+f"((acc)[3])       \
        : "r"(a0), "r"(a1), "r"(a2), "r"(a3), "r"(b0), "r"(b1))

// ---------------- GEMM core ----------------
// C = alpha * A @ B (+bias).  A:[M,K] lda.  B: TRANSB ? [N,K] : [K,N], ldb.
// 128x128 tile, 256 thr (8 warps 2x4), warp tile 64x32, tf32 m16n8k8.
// 3-stage cp.async ring, single __syncthreads per K-chunk.
template <bool TRANSB, bool RND>
__device__ __forceinline__ void gemm_tc(
    const float* __restrict__ A, int lda,
    const float* __restrict__ B, int ldb,
    const float* __restrict__ bias,
    float* __restrict__ C, int ldc,
    int K, float alpha)
{
    constexpr int BS_SZ = TRANSB ? (BN * ASTR) : (BKT * BSTR_NN);

    extern __shared__ float smbase[];
    float* As = smbase;                         // STAGES * BM * ASTR
    float* Bs = smbase + STAGES * BM * ASTR;    // STAGES * BS_SZ

    const int tid = threadIdx.x;
    const int lane = tid & 31;
    const int wid = tid >> 5;
    const int wm = wid & 1;
    const int wn = wid >> 1;
    const int grp = lane >> 2;
    const int qid = lane & 3;

    const int m0 = blockIdx.y * BM;
    const int n0 = blockIdx.x * BN;

    auto issue = [&](int st, int k0) {
        float* Ad = As + st * (BM * ASTR);
        float* Bd = Bs + st * BS_SZ;
        #pragma unroll
        for (int p = 0; p < 2; p++) {
            const int id = tid + 256 * p;
            cp_async16(&Ad[(id >> 2) * ASTR + (id & 3) * 4],
                       &A[(size_t)(m0 + (id >> 2)) * lda + k0 + (id & 3) * 4]);
            if (TRANSB) {
                cp_async16(&Bd[(id >> 2) * ASTR + (id & 3) * 4],
                           &B[(size_t)(n0 + (id >> 2)) * ldb + k0 + (id & 3) * 4]);
            } else {
                cp_async16(&Bd[(id >> 5) * BSTR_NN + (id & 31) * 4],
                           &B[(size_t)(k0 + (id >> 5)) * ldb + n0 + (id & 31) * 4]);
            }
        }
        cp_commit();
    };

    float acc[4][4][4];
    #pragma unroll
    for (int mi = 0; mi < 4; mi++)
        #pragma unroll
        for (int ni = 0; ni < 4; ni++)
            #pragma unroll
            for (int r = 0; r < 4; r++) acc[mi][ni][r] = 0.0f;

    auto compute = [&](int st) {
        const float* Ad = As + st * (BM * ASTR);
        const float* Bd = Bs + st * BS_SZ;
        #pragma unroll
        for (int ks = 0; ks < BKT / 8; ks++) {
            uint32_t af[4][4];
            uint32_t bf[4][2];
            const int kc = ks * 8 + qid;
            #pragma unroll
            for (int mi = 0; mi < 4; mi++) {
                const int r = wm * 64 + mi * 16 + grp;
                af[mi][0] = __float_as_uint(Ad[(r) * ASTR + kc]);
                af[mi][1] = __float_as_uint(Ad[(r + 8) * ASTR + kc]);
                af[mi][2] = __float_as_uint(Ad[(r) * ASTR + kc + 4]);
                af[mi][3] = __float_as_uint(Ad[(r + 8) * ASTR + kc + 4]);
            }
            #pragma unroll
            for (int ni = 0; ni < 4; ni++) {
                const int n = wn * 32 + ni * 8 + grp;
                if (TRANSB) {
                    bf[ni][0] = __float_as_uint(Bd[n * ASTR + kc]);
                    bf[ni][1] = __float_as_uint(Bd[n * ASTR + kc + 4]);
                } else {
                    bf[ni][0] = __float_as_uint(Bd[(kc) * BSTR_NN + n]);
                    bf[ni][1] = __float_as_uint(Bd[(kc + 4) * BSTR_NN + n]);
                }
            }
            #pragma unroll
            for (int mi = 0; mi < 4; mi++)
                #pragma unroll
                for (int ni = 0; ni < 4; ni++)
                    MMA_TF32(acc[mi][ni], af[mi][0], af[mi][1], af[mi][2],
                             af[mi][3], bf[ni][0], bf[ni][1]);
        }
    };

    const int nchunk = K / BKT;        // >= 8 for all call sites

    // prologue: stages 0,1 in flight
    issue(0, 0);
    issue(1, BKT);

    int st = 0;
    for (int c = 0; c < nchunk; c++) {
        if (c == nchunk - 1) cp_wait<0>(); else cp_wait<1>();
        __syncthreads();
        if (c + 2 < nchunk) {
            int wst = st + 2; if (wst >= STAGES) wst -= STAGES;
            issue(wst, (c + 2) * BKT);
        }
        compute(st);
        if (++st == STAGES) st = 0;
    }

    // ---- epilogue ----
    const int row0 = m0 + wm * 64 + grp;
    const int col00 = n0 + wn * 32 + qid * 2;
    #pragma unroll
    for (int mi = 0; mi < 4; mi++) {
        #pragma unroll
        for (int ni = 0; ni < 4; ni++) {
            const int col = col00 + ni * 8;
            float bx = 0.0f, by = 0.0f;
            if (bias) { bx = bias[col]; by = bias[col + 1]; }
            const int r0 = row0 + mi * 16;
            float2 v0, v1;
            v0.x = acc[mi][ni][0] * alpha + bx;
            v0.y = acc[mi][ni][1] * alpha + by;
            v1.x = acc[mi][ni][2] * alpha + bx;
            v1.y = acc[mi][ni][3] * alpha + by;
            if (RND) {
                v0.x = cvt_tf32(v0.x); v0.y = cvt_tf32(v0.y);
                v1.x = cvt_tf32(v1.x); v1.y = cvt_tf32(v1.y);
            }
            *reinterpret_cast<float2*>(&C[(size_t)r0 * ldc + col]) = v0;
            *reinterpret_cast<float2*>(&C[(size_t)(r0 + 8) * ldc + col]) = v1;
        }
    }
}

// ---------------- input rounding pre-pass ----------------
__global__ __launch_bounds__(256)
void k_cvt(const float* __restrict__ in, float* __restrict__ out, int n4)
{
    const int i = blockIdx.x * 256 + threadIdx.x;
    if (i < n4) {
        reinterpret_cast<float4*>(out)[i] =
            cvt_tf32_4(reinterpret_cast<const float4*>(in)[i]);
    }
}

// ---------------- GEMM wrappers ----------------

__global__ __launch_bounds__(256, 2)
void k_proj_z(const float* __restrict__ b)
{
    gemm_tc<false, true>(g_xc, DMODEL, g_wlat, DLAT, b, g_z, DLAT, DMODEL, 1.0f);
}

__global__ __launch_bounds__(256, 2)
void k_proj_q(const float* __restrict__ b)
{
    gemm_tc<false, true>(g_xc, DMODEL, g_wq, DMODEL, b, g_q, DMODEL, DMODEL, 1.0f);
}

__global__ __launch_bounds__(256, 2)
void k_proj_kv(const float* __restrict__ bk, const float* __restrict__ bv)
{
    const int zb = blockIdx.z;
    const int h = zb & (NHEAD - 1);
    const bool isv = zb >= NHEAD;
    const float* w = (isv ? g_wv : g_wk) + (size_t)h * DLAT * DHEAD;
    const float* bb = (isv ? bv : bk) + (size_t)h * DHEAD;
    float* C = (isv ? g_v : g_k) + (size_t)h * ROWS * DHEAD;
    gemm_tc<false, true>(g_z, DLAT, w, DHEAD, bb, C, DHEAD, DLAT, 1.0f);
}

__global__ __launch_bounds__(256, 2)
void k_scores()
{
    const int zb = blockIdx.z;
    const int b = zb >> 4;
    const int h = zb & (NHEAD - 1);
    const float* A = g_q + (size_t)b * SEQ * DMODEL + (size_t)h * DHEAD;
    const float* Bm = g_k + (size_t)h * ROWS * DHEAD + (size_t)b * SEQ * DHEAD;
    float* C = g_scores + (size_t)zb * SEQ * SEQ;
    gemm_tc<true, false>(A, DMODEL, Bm, DHEAD, nullptr, C, SEQ, DHEAD,
                         0.08838834764831845f /* 1/sqrt(128) */);
}

__global__ __launch_bounds__(256, 2)
void k_attn_v()
{
    const int zb = blockIdx.z;
    const int b = zb >> 4;
    const int h = zb & (NHEAD - 1);
    const float* A = g_scores + (size_t)zb * SEQ * SEQ;
    const float* Bm = g_v + (size_t)h * ROWS * DHEAD + (size_t)b * SEQ * DHEAD;
    float* C = g_ao + (size_t)b * SEQ * DMODEL + (size_t)h * DHEAD;
    gemm_tc<false, true>(A, SEQ, Bm, DHEAD, nullptr, C, DMODEL, SEQ, 1.0f);
}

__global__ __launch_bounds__(256, 2)
void k_proj_out(const float* __restrict__ b, float* __restrict__ out)
{
    gemm_tc<false, false>(g_ao, DMODEL, g_wo, DMODEL, b, out, DMODEL, DMODEL, 1.0f);
}

// ---------------- softmax (writes tf32-rounded probs) ----------------
__global__ __launch_bounds__(256)
void k_softmax()
{
    __shared__ float red[9];
    const size_t row = blockIdx.x;
    float* p = g_scores + row * (size_t)SEQ;
    const int t = threadIdx.x;

    float4* pv = reinterpret_cast<float4*>(p);
    float4 a = pv[t * 2];
    float4 c = pv[t * 2 + 1];

    float m = fmaxf(fmaxf(fmaxf(a.x, a.y), fmaxf(a.z, a.w)),
                    fmaxf(fmaxf(c.x, c.y), fmaxf(c.z, c.w)));
    #pragma unroll
    for (int o = 16; o; o >>= 1) m = fmaxf(m, __shfl_xor_sync(0xffffffffu, m, o));
    if ((t & 31) == 0) red[t >> 5] = m;
    __syncthreads();
    if (t < 32) {
        float v = (t < 8) ? red[t] : -3.4e38f;
        #pragma unroll
        for (int o = 4; o; o >>= 1) v = fmaxf(v, __shfl_xor_sync(0xffffffffu, v, o));
        if (t == 0) red[8] = v;
    }
    __syncthreads();
    m = red[8];

    a.x = __expf(a.x - m); a.y = __expf(a.y - m);
    a.z = __expf(a.z - m); a.w = __expf(a.w - m);
    c.x = __expf(c.x - m); c.y = __expf(c.y - m);
    c.z = __expf(c.z - m); c.w = __expf(c.w - m);

    float s = (a.x + a.y + a.z + a.w) + (c.x + c.y + c.z + c.w);
    #pragma unroll
    for (int o = 16; o; o >>= 1) s += __shfl_xor_sync(0xffffffffu, s, o);
    __syncthreads();
    if ((t & 31) == 0) red[t >> 5] = s;
    __syncthreads();
    if (t < 32) {
        float v = (t < 8) ? red[t] : 0.0f;
        #pragma unroll
        for (int o = 4; o; o >>= 1) v += __shfl_xor_sync(0xffffffffu, v, o);
        if (t == 0) red[8] = v;
    }
    __syncthreads();
    const float inv = 1.0f / red[8];

    a.x *= inv; a.y *= inv; a.z *= inv; a.w *= inv;
    c.x *= inv; c.y *= inv; c.z *= inv; c.w *= inv;
    pv[t * 2] = cvt_tf32_4(a);
    pv[t * 2 + 1] = cvt_tf32_4(c);
}

// ---------------- launch ----------------

extern "C" void kernel_launch(void* const* d_in, const int* in_sizes, int n_in,
                              void* d_out, int out_size)
{
    const float* x        = (const float*)d_in[0];
    const float* w_latent = (const float*)d_in[1];
    const float* b_latent = (const float*)d_in[2];
    const float* w_q      = (const float*)d_in[3];
    const float* b_q      = (const float*)d_in[4];
    const float* w_k      = (const float*)d_in[5];
    const float* b_k      = (const float*)d_in[6];
    const float* w_v      = (const float*)d_in[7];
    const float* b_v      = (const float*)d_in[8];
    const float* w_o      = (const float*)d_in[9];
    const float* b_o      = (const float*)d_in[10];
    float* out            = (float*)d_out;

    dim3 blk(256);

    cudaFuncSetAttribute(k_proj_z,
        cudaFuncAttributeMaxDynamicSharedMemorySize, SMEM_N);
    cudaFuncSetAttribute(k_proj_q,
        cudaFuncAttributeMaxDynamicSharedMemorySize, SMEM_N);
    cudaFuncSetAttribute(k_proj_kv,
        cudaFuncAttributeMaxDynamicSharedMemorySize, SMEM_N);
    cudaFuncSetAttribute(k_attn_v,
        cudaFuncAttributeMaxDynamicSharedMemorySize, SMEM_N);
    cudaFuncSetAttribute(k_proj_out,
        cudaFuncAttributeMaxDynamicSharedMemorySize, SMEM_N);
    cudaFuncSetAttribute(k_scores,
        cudaFuncAttributeMaxDynamicSharedMemorySize, SMEM_T);

    float *p_xc, *p_wlat, *p_wq, *p_wk, *p_wv, *p_wo;
    cudaGetSymbolAddress((void**)&p_xc,   g_xc);
    cudaGetSymbolAddress((void**)&p_wlat, g_wlat);
    cudaGetSymbolAddress((void**)&p_wq,   g_wq);
    cudaGetSymbolAddress((void**)&p_wk,   g_wk);
    cudaGetSymbolAddress((void**)&p_wv,   g_wv);
    cudaGetSymbolAddress((void**)&p_wo,   g_wo);

    auto cvt = [&](const float* src, float* dst, size_t n) {
        const int n4 = (int)(n / 4);
        k_cvt<<<(n4 + 255) / 256, blk>>>(src, dst, n4);
    };
    cvt(x,        p_xc,   (size_t)ROWS * DMODEL);
    cvt(w_latent, p_wlat, (size_t)DMODEL * DLAT);
    cvt(w_q,      p_wq,   (size_t)DMODEL * DMODEL);
    cvt(w_k,      p_wk,   (size_t)NHEAD * DLAT * DHEAD);
    cvt(w_v,      p_wv,   (size_t)NHEAD * DLAT * DHEAD);
    cvt(w_o,      p_wo,   (size_t)DMODEL * DMODEL);

    k_proj_z<<<dim3(DLAT / BN, ROWS / BM), blk, SMEM_N>>>(b_latent);
    k_proj_q<<<dim3(DMODEL / BN, ROWS / BM), blk, SMEM_N>>>(b_q);
    k_proj_kv<<<dim3(DHEAD / BN, ROWS / BM, 2 * NHEAD), blk, SMEM_N>>>(b_k, b_v);
    k_scores<<<dim3(SEQ / BN, SEQ / BM, BDIM * NHEAD), blk, SMEM_T>>>();
    k_softmax<<<dim3(BDIM * NHEAD * SEQ), blk>>>();
    k_attn_v<<<dim3(DHEAD / BN, SEQ / BM, BDIM * NHEAD), blk, SMEM_N>>>();
    k_proj_out<<<dim3(DMODEL / BN, ROWS / BM), blk, SMEM_N>>>(b_o, out);
}

// round 14
// speedup vs baseline: 2.3410x; 1.6312x over previous
#include <cuda_runtime.h>
#include <cuda_fp16.h>
#include <cstdint>

// ---------------------------------------------------------------------------
// MLA forward. fp16 mma.sync m16n8k16 (fp32 accumulate), 3-stage cp.async.
// All GEMM operands stored fp16; weights pre-transposed to [N,K] so GEMMs
// run in the conflict-free TRANSB layout (except attn_v's V, K-major).
//   B=2, S=2048, D=2048, H=16, DH=128, DL=512
// ---------------------------------------------------------------------------

#define BDIM 2
#define SEQ 2048
#define DMODEL 2048
#define NHEAD 16
#define DHEAD 128
#define DLAT 512
#define ROWS (BDIM * SEQ)          // 4096

// fp16 intermediates
__device__ __half g_xh[(size_t)ROWS * DMODEL];
__device__ __half g_z[(size_t)ROWS * DLAT];
__device__ __half g_q[(size_t)ROWS * DMODEL];
__device__ __half g_k[(size_t)NHEAD * ROWS * DHEAD];
__device__ __half g_v[(size_t)NHEAD * ROWS * DHEAD];
__device__ __half g_scores[(size_t)BDIM * NHEAD * SEQ * SEQ];  // 256 MB
__device__ __half g_ao[(size_t)ROWS * DMODEL];

// fp16 transposed weights [N][K]
__device__ __half g_wlat_t[(size_t)DLAT * DMODEL];
__device__ __half g_wq_t[(size_t)DMODEL * DMODEL];
__device__ __half g_wk_t[(size_t)NHEAD * DHEAD * DLAT];
__device__ __half g_wv_t[(size_t)NHEAD * DHEAD * DLAT];
__device__ __half g_wo_t[(size_t)DMODEL * DMODEL];

#define BM 128
#define BN 128
#define BKT 32                      // halves per K-chunk (2 x k16 steps)
#define STAGES 3
#define ASTR 40                     // BKT + 8 halves (conflict-free)
#define BSTR_NN 136                 // BN + 8 halves

// smem bytes (halves * 2)
#define SMEM_T  (STAGES * (BM * ASTR + BN * ASTR) * 2)        // 61440
#define SMEM_N  (STAGES * (BM * ASTR + BKT * BSTR_NN) * 2)    // 56832

// ---------------- helpers ----------------

__device__ __forceinline__ void cp_async16(void* smem_dst, const void* gmem_src)
{
    uint32_t s = (uint32_t)__cvta_generic_to_shared(smem_dst);
    asm volatile("cp.async.cg.shared.global [%0], [%1], 16;\n" :: "r"(s), "l"(gmem_src));
}
__device__ __forceinline__ void cp_commit()
{
    asm volatile("cp.async.commit_group;\n");
}
template <int N>
__device__ __forceinline__ void cp_wait()
{
    asm volatile("cp.async.wait_group %0;\n" :: "n"(N));
}

__device__ __forceinline__ uint32_t packh(__half lo, __half hi)
{
    return (uint32_t)__half_as_ushort(lo) | ((uint32_t)__half_as_ushort(hi) << 16);
}

#define MMA_F16(acc, a0, a1, a2, a3, b0, b1)                                   \
    asm volatile(                                                              \
        "mma.sync.aligned.m16n8k16.row.col.f32.f16.f16.f32 "                   \
        "{%0,%1,%2,%3},{%4,%5,%6,%7},{%8,%9},{%0,%1,%2,%3};\n"                 \
        : "+f"((acc)[0]), "+f"((acc)[1]), "+f"((acc)[2]), "+f"((acc)[3])       \
        : "r"(a0), "r"(a1), "r"(a2), "r"(a3), "r"(b0), "r"(b1))

// ---------------- GEMM core ----------------
// C = alpha * A @ B (+bias).  A:[M,K] half, lda.
// B: TRANSB ? [N,K] half : [K,N] half, ldb.  C: OUTH ? half : float.
// 128x128 tile, 256 thr (8 warps 2x4), warp tile 64x32, fp16 m16n8k16.
// 3-stage cp.async ring, one __syncthreads per 32-deep K-chunk.
template <bool TRANSB, bool OUTH>
__device__ __forceinline__ void gemm_h(
    const __half* __restrict__ A, int lda,
    const __half* __restrict__ B, int ldb,
    const float* __restrict__ bias,
    void* __restrict__ Cp, int ldc,
    int K, float alpha)
{
    constexpr int BS_SZ = TRANSB ? (BN * ASTR) : (BKT * BSTR_NN);

    extern __shared__ __half smh[];
    __half* As = smh;                          // STAGES * BM * ASTR
    __half* Bs = smh + STAGES * BM * ASTR;     // STAGES * BS_SZ

    const int tid = threadIdx.x;
    const int lane = tid & 31;
    const int wid = tid >> 5;
    const int wm = wid & 1;
    const int wn = wid >> 1;
    const int grp = lane >> 2;
    const int qid = lane & 3;

    const int m0 = blockIdx.y * BM;
    const int n0 = blockIdx.x * BN;

    // per chunk: A tile 128x32 halves = 512 x 16B chunks; B same (TRANSB) or
    // 32x128 halves = 512 chunks (NN). 2 per thread per array.
    auto issue = [&](int st, int k0) {
        __half* Ad = As + st * (BM * ASTR);
        __half* Bd = Bs + st * BS_SZ;
        #pragma unroll
        for (int p = 0; p < 2; p++) {
            const int id = tid + 256 * p;
            const int row = id >> 2, ch = id & 3;        // 4 chunks of 8 halves
            cp_async16(&Ad[row * ASTR + ch * 8],
                       &A[(size_t)(m0 + row) * lda + k0 + ch * 8]);
            if (TRANSB) {
                cp_async16(&Bd[row * ASTR + ch * 8],
                           &B[(size_t)(n0 + row) * ldb + k0 + ch * 8]);
            } else {
                const int brow = id >> 4, bch = id & 15; // 16 chunks of 8 halves
                cp_async16(&Bd[brow * BSTR_NN + bch * 8],
                           &B[(size_t)(k0 + brow) * ldb + n0 + bch * 8]);
            }
        }
        cp_commit();
    };

    float acc[4][4][4];
    #pragma unroll
    for (int mi = 0; mi < 4; mi++)
        #pragma unroll
        for (int ni = 0; ni < 4; ni++)
            #pragma unroll
            for (int r = 0; r < 4; r++) acc[mi][ni][r] = 0.0f;

    auto compute = [&](int st) {
        const __half* Ad = As + st * (BM * ASTR);
        const __half* Bd = Bs + st * BS_SZ;
        #pragma unroll
        for (int ks = 0; ks < BKT / 16; ks++) {
            uint32_t af[4][4];
            uint32_t bf[4][2];
            const int kc = ks * 16 + qid * 2;
            #pragma unroll
            for (int mi = 0; mi < 4; mi++) {
                const int r = wm * 64 + mi * 16 + grp;
                af[mi][0] = *reinterpret_cast<const uint32_t*>(&Ad[(r) * ASTR + kc]);
                af[mi][1] = *reinterpret_cast<const uint32_t*>(&Ad[(r + 8) * ASTR + kc]);
                af[mi][2] = *reinterpret_cast<const uint32_t*>(&Ad[(r) * ASTR + kc + 8]);
                af[mi][3] = *reinterpret_cast<const uint32_t*>(&Ad[(r + 8) * ASTR + kc + 8]);
            }
            #pragma unroll
            for (int ni = 0; ni < 4; ni++) {
                const int n = wn * 32 + ni * 8 + grp;
                if (TRANSB) {
                    bf[ni][0] = *reinterpret_cast<const uint32_t*>(&Bd[n * ASTR + kc]);
                    bf[ni][1] = *reinterpret_cast<const uint32_t*>(&Bd[n * ASTR + kc + 8]);
                } else {
                    bf[ni][0] = packh(Bd[(kc) * BSTR_NN + n], Bd[(kc + 1) * BSTR_NN + n]);
                    bf[ni][1] = packh(Bd[(kc + 8) * BSTR_NN + n], Bd[(kc + 9) * BSTR_NN + n]);
                }
            }
            #pragma unroll
            for (int mi = 0; mi < 4; mi++)
                #pragma unroll
                for (int ni = 0; ni < 4; ni++)
                    MMA_F16(acc[mi][ni], af[mi][0], af[mi][1], af[mi][2],
                            af[mi][3], bf[ni][0], bf[ni][1]);
        }
    };

    const int nchunk = K / BKT;        // >= 4 for all call sites

    issue(0, 0);
    issue(1, BKT);

    int st = 0;
    for (int c = 0; c < nchunk; c++) {
        if (c == nchunk - 1) cp_wait<0>(); else cp_wait<1>();
        __syncthreads();
        if (c + 2 < nchunk) {
            int wst = st + 2; if (wst >= STAGES) wst -= STAGES;
            issue(wst, (c + 2) * BKT);
        }
        compute(st);
        if (++st == STAGES) st = 0;
    }

    // ---- epilogue ----
    const int row0 = m0 + wm * 64 + grp;
    const int col00 = n0 + wn * 32 + qid * 2;
    #pragma unroll
    for (int mi = 0; mi < 4; mi++) {
        #pragma unroll
        for (int ni = 0; ni < 4; ni++) {
            const int col = col00 + ni * 8;
            float bx = 0.0f, by = 0.0f;
            if (bias) { bx = bias[col]; by = bias[col + 1]; }
            const int r0 = row0 + mi * 16;
            float2 v0, v1;
            v0.x = acc[mi][ni][0] * alpha + bx;
            v0.y = acc[mi][ni][1] * alpha + by;
            v1.x = acc[mi][ni][2] * alpha + bx;
            v1.y = acc[mi][ni][3] * alpha + by;
            if (OUTH) {
                __half* Ch = (__half*)Cp;
                *reinterpret_cast<__half2*>(&Ch[(size_t)r0 * ldc + col]) =
                    __floats2half2_rn(v0.x, v0.y);
                *reinterpret_cast<__half2*>(&Ch[(size_t)(r0 + 8) * ldc + col]) =
                    __floats2half2_rn(v1.x, v1.y);
            } else {
                float* Cf = (float*)Cp;
                *reinterpret_cast<float2*>(&Cf[(size_t)r0 * ldc + col]) = v0;
                *reinterpret_cast<float2*>(&Cf[(size_t)(r0 + 8) * ldc + col]) = v1;
            }
        }
    }
}

// ---------------- conversion / transpose pre-passes ----------------

// plain fp32 -> fp16 (4 elements/thread)
__global__ __launch_bounds__(256)
void k_cvt_h(const float* __restrict__ in, __half* __restrict__ out, int n4)
{
    const int i = blockIdx.x * 256 + threadIdx.x;
    if (i < n4) {
        float4 v = reinterpret_cast<const float4*>(in)[i];
        reinterpret_cast<__half2*>(out)[i * 2]     = __floats2half2_rn(v.x, v.y);
        reinterpret_cast<__half2*>(out)[i * 2 + 1] = __floats2half2_rn(v.z, v.w);
    }
}

// tiled transpose: in fp32 [R][C] -> out fp16 [C][R]  (per blockIdx.z slice)
__global__ __launch_bounds__(256)
void k_tr(const float* __restrict__ in, __half* __restrict__ out, int R, int C)
{
    __shared__ __half t[32][33];
    const float* src = in + (size_t)blockIdx.z * R * C;
    __half* dst = out + (size_t)blockIdx.z * R * C;
    const int x = blockIdx.x * 32 + threadIdx.x;
    const int y0 = blockIdx.y * 32 + threadIdx.y;
    #pragma unroll
    for (int i = 0; i < 32; i += 8) {
        const int y = y0 + i;
        if (y < R && x < C)
            t[threadIdx.y + i][threadIdx.x] = __float2half_rn(src[(size_t)y * C + x]);
    }
    __syncthreads();
    const int ox = blockIdx.y * 32 + threadIdx.x;   // col of output (= input row)
    const int oy0 = blockIdx.x * 32 + threadIdx.y;  // row of output (= input col)
    #pragma unroll
    for (int i = 0; i < 32; i += 8) {
        const int oy = oy0 + i;
        if (oy < C && ox < R)
            dst[(size_t)oy * R + ox] = t[threadIdx.x][threadIdx.y + i];
    }
}

// ---------------- GEMM wrappers ----------------

__global__ __launch_bounds__(256, 2)
void k_proj_z(const float* __restrict__ b)
{
    gemm_h<true, true>(g_xh, DMODEL, g_wlat_t, DMODEL, b, g_z, DLAT, DMODEL, 1.0f);
}

__global__ __launch_bounds__(256, 2)
void k_proj_q(const float* __restrict__ b)
{
    gemm_h<true, true>(g_xh, DMODEL, g_wq_t, DMODEL, b, g_q, DMODEL, DMODEL, 1.0f);
}

__global__ __launch_bounds__(256, 2)
void k_proj_kv(const float* __restrict__ bk, const float* __restrict__ bv)
{
    const int zb = blockIdx.z;
    const int h = zb & (NHEAD - 1);
    const bool isv = zb >= NHEAD;
    const __half* w = (isv ? g_wv_t : g_wk_t) + (size_t)h * DLAT * DHEAD;
    const float* bb = (isv ? bv : bk) + (size_t)h * DHEAD;
    __half* C = (isv ? g_v : g_k) + (size_t)h * ROWS * DHEAD;
    gemm_h<true, true>(g_z, DLAT, w, DLAT, bb, C, DHEAD, DLAT, 1.0f);
}

__global__ __launch_bounds__(256, 2)
void k_scores()
{
    const int zb = blockIdx.z;
    const int b = zb >> 4;
    const int h = zb & (NHEAD - 1);
    const __half* A = g_q + (size_t)b * SEQ * DMODEL + (size_t)h * DHEAD;
    const __half* Bm = g_k + (size_t)h * ROWS * DHEAD + (size_t)b * SEQ * DHEAD;
    __half* C = g_scores + (size_t)zb * SEQ * SEQ;
    gemm_h<true, true>(A, DMODEL, Bm, DHEAD, nullptr, C, SEQ, DHEAD,
                       0.08838834764831845f /* 1/sqrt(128) */);
}

__global__ __launch_bounds__(256, 2)
void k_attn_v()
{
    const int zb = blockIdx.z;
    const int b = zb >> 4;
    const int h = zb & (NHEAD - 1);
    const __half* A = g_scores + (size_t)zb * SEQ * SEQ;
    const __half* Bm = g_v + (size_t)h * ROWS * DHEAD + (size_t)b * SEQ * DHEAD;
    __half* C = g_ao + (size_t)b * SEQ * DMODEL + (size_t)h * DHEAD;
    gemm_h<false, true>(A, SEQ, Bm, DHEAD, nullptr, C, DMODEL, SEQ, 1.0f);
}

__global__ __launch_bounds__(256, 2)
void k_proj_out(const float* __restrict__ b, float* __restrict__ out)
{
    gemm_h<true, false>(g_ao, DMODEL, g_wo_t, DMODEL, b, out, DMODEL, DMODEL, 1.0f);
}

// ---------------- softmax on fp16 scores ----------------
// one block / row of 2048; each thread owns 8 contiguous halves (one uint4)
__global__ __launch_bounds__(256)
void k_softmax()
{
    __shared__ float red[9];
    const size_t row = blockIdx.x;
    __half* p = g_scores + row * (size_t)SEQ;
    const int t = threadIdx.x;

    __half2* pv = reinterpret_cast<__half2*>(p) + t * 4;
    float2 f[4];
    #pragma unroll
    for (int i = 0; i < 4; i++) f[i] = __half22float2(pv[i]);

    float m = -3.4e38f;
    #pragma unroll
    for (int i = 0; i < 4; i++) m = fmaxf(m, fmaxf(f[i].x, f[i].y));
    #pragma unroll
    for (int o = 16; o; o >>= 1) m = fmaxf(m, __shfl_xor_sync(0xffffffffu, m, o));
    if ((t & 31) == 0) red[t >> 5] = m;
    __syncthreads();
    if (t < 32) {
        float v = (t < 8) ? red[t] : -3.4e38f;
        #pragma unroll
        for (int o = 4; o; o >>= 1) v = fmaxf(v, __shfl_xor_sync(0xffffffffu, v, o));
        if (t == 0) red[8] = v;
    }
    __syncthreads();
    m = red[8];

    float s = 0.0f;
    #pragma unroll
    for (int i = 0; i < 4; i++) {
        f[i].x = __expf(f[i].x - m);
        f[i].y = __expf(f[i].y - m);
        s += f[i].x + f[i].y;
    }
    #pragma unroll
    for (int o = 16; o; o >>= 1) s += __shfl_xor_sync(0xffffffffu, s, o);
    __syncthreads();
    if ((t & 31) == 0) red[t >> 5] = s;
    __syncthreads();
    if (t < 32) {
        float v = (t < 8) ? red[t] : 0.0f;
        #pragma unroll
        for (int o = 4; o; o >>= 1) v += __shfl_xor_sync(0xffffffffu, v, o);
        if (t == 0) red[8] = v;
    }
    __syncthreads();
    const float inv = 1.0f / red[8];

    #pragma unroll
    for (int i = 0; i < 4; i++)
        pv[i] = __floats2half2_rn(f[i].x * inv, f[i].y * inv);
}

// ---------------- launch ----------------

extern "C" void kernel_launch(void* const* d_in, const int* in_sizes, int n_in,
                              void* d_out, int out_size)
{
    const float* x        = (const float*)d_in[0];
    const float* w_latent = (const float*)d_in[1];
    const float* b_latent = (const float*)d_in[2];
    const float* w_q      = (const float*)d_in[3];
    const float* b_q      = (const float*)d_in[4];
    const float* w_k      = (const float*)d_in[5];
    const float* b_k      = (const float*)d_in[6];
    const float* w_v      = (const float*)d_in[7];
    const float* b_v      = (const float*)d_in[8];
    const float* w_o      = (const float*)d_in[9];
    const float* b_o      = (const float*)d_in[10];
    float* out            = (float*)d_out;

    dim3 blk(256);
    dim3 tblk(32, 8);

    cudaFuncSetAttribute(k_proj_z,   cudaFuncAttributeMaxDynamicSharedMemorySize, SMEM_T);
    cudaFuncSetAttribute(k_proj_q,   cudaFuncAttributeMaxDynamicSharedMemorySize, SMEM_T);
    cudaFuncSetAttribute(k_proj_kv,  cudaFuncAttributeMaxDynamicSharedMemorySize, SMEM_T);
    cudaFuncSetAttribute(k_scores,   cudaFuncAttributeMaxDynamicSharedMemorySize, SMEM_T);
    cudaFuncSetAttribute(k_attn_v,   cudaFuncAttributeMaxDynamicSharedMemorySize, SMEM_N);
    cudaFuncSetAttribute(k_proj_out, cudaFuncAttributeMaxDynamicSharedMemorySize, SMEM_T);

    __half *p_xh, *p_wlat, *p_wq, *p_wk, *p_wv, *p_wo;
    cudaGetSymbolAddress((void**)&p_xh,   g_xh);
    cudaGetSymbolAddress((void**)&p_wlat, g_wlat_t);
    cudaGetSymbolAddress((void**)&p_wq,   g_wq_t);
    cudaGetSymbolAddress((void**)&p_wk,   g_wk_t);
    cudaGetSymbolAddress((void**)&p_wv,   g_wv_t);
    cudaGetSymbolAddress((void**)&p_wo,   g_wo_t);

    // x -> fp16 (no transpose; it's the A operand)
    {
        const int n4 = (int)((size_t)ROWS * DMODEL / 4);
        k_cvt_h<<<(n4 + 255) / 256, blk>>>(x, p_xh, n4);
    }
    // weights -> fp16 transposed [N][K]
    k_tr<<<dim3(DLAT / 32, DMODEL / 32), tblk>>>(w_latent, p_wlat, DMODEL, DLAT);
    k_tr<<<dim3(DMODEL / 32, DMODEL / 32), tblk>>>(w_q, p_wq, DMODEL, DMODEL);
    k_tr<<<dim3(DHEAD / 32, DLAT / 32, NHEAD), tblk>>>(w_k, p_wk, DLAT, DHEAD);
    k_tr<<<dim3(DHEAD / 32, DLAT / 32, NHEAD), tblk>>>(w_v, p_wv, DLAT, DHEAD);
    k_tr<<<dim3(DMODEL / 32, DMODEL / 32), tblk>>>(w_o, p_wo, DMODEL, DMODEL);

    k_proj_z<<<dim3(DLAT / BN, ROWS / BM), blk, SMEM_T>>>(b_latent);
    k_proj_q<<<dim3(DMODEL / BN, ROWS / BM), blk, SMEM_T>>>(b_q);
    k_proj_kv<<<dim3(DHEAD / BN, ROWS / BM, 2 * NHEAD), blk, SMEM_T>>>(b_k, b_v);
    k_scores<<<dim3(SEQ / BN, SEQ / BM, BDIM * NHEAD), blk, SMEM_T>>>();
    k_softmax<<<dim3(BDIM * NHEAD * SEQ), blk>>>();
    k_attn_v<<<dim3(DHEAD / BN, SEQ / BM, BDIM * NHEAD), blk, SMEM_N>>>();
    k_proj_out<<<dim3(DMODEL / BN, ROWS / BM), blk, SMEM_T>>>(b_o, out);
}